// round 4
// baseline (speedup 1.0000x reference)
#include <cuda_runtime.h>
#include <math.h>

#define SEQ  262144
#define NIN  100
#define NHID 40

// Scratch (device globals — no allocation allowed in kernel_launch)
__device__ float g_A[SEQ * NHID];   // Wx @ x_i for all i   (~42 MB, L2-resident)
__device__ float g_T[SEQ * NHID];   // hidden states t_i    (~42 MB)

// ---------------- packed f32x2 helpers (sm_100+) ----------------
__device__ __forceinline__ unsigned long long fma2(unsigned long long a,
                                                   unsigned long long b,
                                                   unsigned long long c) {
    unsigned long long d;
    asm("fma.rn.f32x2 %0, %1, %2, %3;" : "=l"(d) : "l"(a), "l"(b), "l"(c));
    return d;
}
__device__ __forceinline__ float2 unpack2(unsigned long long v) {
    float2 r;
    asm("mov.b64 {%0, %1}, %2;" : "=f"(r.x), "=f"(r.y) : "l"(v));
    return r;
}

// ---------------- Kernel 1: A[i][h] = dot(s[i,:], Wx[h,:]) ----------------
__global__ void rnn_pre_kernel(const float* __restrict__ s,
                               const float* __restrict__ Wx) {
    __shared__ float wx[NHID * 101];   // pad 101 -> conflict-free LDS across h
    for (int k = threadIdx.x; k < NHID * NIN; k += blockDim.x) {
        int h = k / NIN, j = k - h * NIN;
        wx[h * 101 + j] = Wx[k];
    }
    __syncthreads();

    const int total = SEQ * NHID;
    for (int idx = blockIdx.x * blockDim.x + threadIdx.x; idx < total;
         idx += gridDim.x * blockDim.x) {
        int i = idx / NHID;
        int h = idx - i * NHID;
        const float4* s4 = reinterpret_cast<const float4*>(s + i * NIN);
        const float* w = wx + h * 101;
        float acc = 0.f;
#pragma unroll
        for (int j = 0; j < 25; j++) {
            float4 v = __ldg(s4 + j);   // broadcast within warp (same i)
            acc += v.x * w[4 * j + 0];
            acc += v.y * w[4 * j + 1];
            acc += v.z * w[4 * j + 2];
            acc += v.w * w[4 * j + 3];
        }
        g_A[idx] = acc;
    }
}

// ---------------- Kernel 2: sequential scan (single block, latency-bound) --
// 96 threads. Thread (h = tid>>1, q = tid&1) computes half of dot(Wh[h,:], t)
// (j = q*20 .. q*20+19) with packed f32x2 FMAs; partner-combine via shfl.xor(1).
// t double-buffered in SMEM; one __syncthreads per step.
// A[] prefetched 4 steps ahead into a register ring.
__global__ void rnn_scan_kernel(const float* __restrict__ t0,
                                const float* __restrict__ Wh,
                                float* __restrict__ outT) {
    __shared__ __align__(16) float ts[2][48];
    const int tid = threadIdx.x;
    const bool act = (tid < 2 * NHID);     // 80 active lanes
    const int hh = act ? (tid >> 1) : 0;
    const int q = tid & 1;

    if (tid < NHID) ts[0][tid] = t0[tid];

    // Pack this thread's 20 Wh weights into 10 f32x2 registers.
    unsigned long long wv[10];
    const unsigned long long* whu =
        reinterpret_cast<const unsigned long long*>(Wh + hh * NHID + q * 20);
#pragma unroll
    for (int k = 0; k < 10; k++) wv[k] = whu[k];

    const float* Ap = g_A + hh;
    float* Tp = g_T + hh;

    // Prefetch ring, distance 4
    float apf[4];
#pragma unroll
    for (int k = 0; k < 4; k++) apf[k] = __ldg(Ap + k * NHID);

    __syncthreads();

    for (int i = 0; i < SEQ; i += 4) {
#pragma unroll
        for (int u = 0; u < 4; u++) {
            const int rb = u & 1, wb = rb ^ 1;
            const ulonglong2* tp =
                reinterpret_cast<const ulonglong2*>(&ts[rb][q * 20]);
            ulonglong2 p0 = tp[0], p1 = tp[1], p2 = tp[2], p3 = tp[3], p4 = tp[4];

            unsigned long long acc0 = fma2(wv[0], p0.x, 0ULL);
            unsigned long long acc1 = fma2(wv[1], p0.y, 0ULL);
            acc0 = fma2(wv[2], p1.x, acc0);
            acc1 = fma2(wv[3], p1.y, acc1);
            acc0 = fma2(wv[4], p2.x, acc0);
            acc1 = fma2(wv[5], p2.y, acc1);
            acc0 = fma2(wv[6], p3.x, acc0);
            acc1 = fma2(wv[7], p3.y, acc1);
            acc0 = fma2(wv[8], p4.x, acc0);
            acc1 = fma2(wv[9], p4.y, acc1);

            float2 f0 = unpack2(acc0), f1 = unpack2(acc1);
            float part = (f0.x + f0.y) + (f1.x + f1.y);
            part += __shfl_xor_sync(0xFFFFFFFFu, part, 1);  // partner half

            float tn = tanhf(part + apf[u]);

            if (act && q == 0) {
                ts[wb][hh] = tn;
                Tp[(i + u) * NHID] = tn;   // fire-and-forget
            }
            // prefetch A for step i+u+4 (clamped)
            int nx = i + u + 4;
            if (nx > SEQ - 1) nx = SEQ - 1;
            apf[u] = __ldg(Ap + nx * NHID);

            __syncthreads();
        }
    }
    // SEQ % 2 == 0 -> final state sits in ts[0]
    if (outT != nullptr && tid < NHID) outT[tid] = ts[0][tid];
}

// ---------------- Kernel 3: y[i] = softmax(Wy @ t_i) ----------------
// One warp per row; lane computes outputs k = c*32 + lane, c = 0..3.
__global__ void rnn_softmax_kernel(const float* __restrict__ Wy,
                                   float* __restrict__ outY) {
    __shared__ float wy[NIN * 41];               // pad 41 -> conflict-free
    __shared__ __align__(16) float trow[4][40];  // one t row per warp
    for (int k = threadIdx.x; k < NIN * NHID; k += blockDim.x) {
        int r = k / NHID, c = k - r * NHID;
        wy[r * 41 + c] = Wy[k];
    }
    __syncthreads();

    const int warp = threadIdx.x >> 5;
    const int lane = threadIdx.x & 31;
    const float NEG_INF = -__int_as_float(0x7f800000);

    for (int row = blockIdx.x * 4 + warp; row < SEQ; row += gridDim.x * 4) {
        if (lane < 10)
            reinterpret_cast<float4*>(trow[warp])[lane] =
                reinterpret_cast<const float4*>(g_T + (size_t)row * NHID)[lane];
        __syncwarp();

        float z[4];
#pragma unroll
        for (int c = 0; c < 4; c++) {
            int k = c * 32 + lane;
            if (k < NIN) {
                const float* w = wy + k * 41;
                float acc = 0.f;
#pragma unroll
                for (int j = 0; j < NHID; j++) acc += trow[warp][j] * w[j];
                z[c] = acc;
            } else {
                z[c] = NEG_INF;
            }
        }
        float m = fmaxf(fmaxf(z[0], z[1]), fmaxf(z[2], z[3]));
#pragma unroll
        for (int o = 16; o; o >>= 1)
            m = fmaxf(m, __shfl_xor_sync(0xFFFFFFFFu, m, o));

        float e[4];
        float ssum = 0.f;
#pragma unroll
        for (int c = 0; c < 4; c++) {
            e[c] = (z[c] > -1e30f) ? expf(z[c] - m) : 0.f;
            ssum += e[c];
        }
#pragma unroll
        for (int o = 16; o; o >>= 1)
            ssum += __shfl_xor_sync(0xFFFFFFFFu, ssum, o);
        float inv = 1.0f / ssum;

#pragma unroll
        for (int c = 0; c < 4; c++) {
            int k = c * 32 + lane;
            if (k < NIN) outY[(size_t)row * NIN + k] = e[c] * inv;
        }
        __syncwarp();  // trow reused next iteration
    }
}

// ---------------- launch ----------------
extern "C" void kernel_launch(void* const* d_in, const int* in_sizes, int n_in,
                              void* d_out, int out_size) {
    const float* s  = (const float*)d_in[0];   // [262144,100]
    const float* t0 = (const float*)d_in[1];   // [40]
    const float* Wx = (const float*)d_in[2];   // [40,100]
    const float* Wh = (const float*)d_in[3];   // [40,40]
    const float* Wy = (const float*)d_in[4];   // [100,40]
    float* out = (float*)d_out;

    // Output tuple is (t_final, ys). Be defensive in case only ys is kept.
    float* tout;
    float* yout;
    if (out_size == SEQ * NIN) {
        tout = nullptr;
        yout = out;
    } else {
        tout = out;            // first 40 floats
        yout = out + NHID;     // then [262144,100]
    }

    rnn_pre_kernel<<<2048, 256>>>(s, Wx);
    rnn_scan_kernel<<<1, 96>>>(t0, Wh, tout);
    rnn_softmax_kernel<<<1184, 128>>>(Wy, yout);
}

// round 7
// speedup vs baseline: 1.1594x; 1.1594x over previous
#include <cuda_runtime.h>
#include <math.h>

#define SEQ  262144
#define NIN  100
#define NHID 40
#define PF   8          // A-prefetch distance / inner unroll (SEQ % PF == 0)

// Scratch (device globals — no allocation allowed in kernel_launch)
__device__ float g_A[SEQ * NHID];   // Wx @ x_i for all i   (~42 MB, mostly L2-resident)
__device__ float g_T[SEQ * NHID];   // hidden states t_i    (~42 MB)

// ---------------- packed f32x2 helpers (sm_100+) ----------------
__device__ __forceinline__ unsigned long long fma2(unsigned long long a,
                                                   unsigned long long b,
                                                   unsigned long long c) {
    unsigned long long d;
    asm("fma.rn.f32x2 %0, %1, %2, %3;" : "=l"(d) : "l"(a), "l"(b), "l"(c));
    return d;
}
__device__ __forceinline__ unsigned long long mul2(unsigned long long a,
                                                   unsigned long long b) {
    unsigned long long d;
    asm("mul.rn.f32x2 %0, %1, %2;" : "=l"(d) : "l"(a), "l"(b));
    return d;
}
__device__ __forceinline__ unsigned long long add2(unsigned long long a,
                                                   unsigned long long b) {
    unsigned long long d;
    asm("add.rn.f32x2 %0, %1, %2;" : "=l"(d) : "l"(a), "l"(b));
    return d;
}
__device__ __forceinline__ float2 unpack2(unsigned long long v) {
    float2 r;
    asm("mov.b64 {%0, %1}, %2;" : "=f"(r.x), "=f"(r.y) : "l"(v));
    return r;
}

// Fast accurate-enough tanh: tanh(x) = 1 - 2/(e^{2x}+1).
// ex2.approx (~2 ulp) + rcp.approx (~2 ulp): total abs err ~2e-7/step.
// Saturates cleanly: x>>0 -> e2=inf -> rcp=0 -> 1;  x<<0 -> e2=0 -> 1-2 = -1.
__device__ __forceinline__ float fast_tanh(float x) {
    float e;
    asm("ex2.approx.f32 %0, %1;" : "=f"(e) : "f"(x * 2.8853900817779268f)); // 2*log2(e)
    float r;
    asm("rcp.approx.f32 %0, %1;" : "=f"(r) : "f"(e + 1.0f));
    return fmaf(-2.0f, r, 1.0f);
}

// ---------------- Kernel 1: A[i][h] = dot(s[i,:], Wx[h,:]) ----------------
// wxT[j][h] transposed in SMEM; each thread computes 4 h-outputs for one row i.
// All SMEM reads are LDS.128; s row read once per 4 outputs.
__global__ void rnn_pre_kernel(const float* __restrict__ s,
                               const float* __restrict__ Wx) {
    __shared__ __align__(16) float wxT[NIN][NHID];   // 16 KB
    for (int k = threadIdx.x; k < NHID * NIN; k += blockDim.x) {
        int hh = k / NIN, j = k - hh * NIN;
        wxT[j][hh] = Wx[k];
    }
    __syncthreads();

    const int total = SEQ * 10;   // 10 h-groups of 4 per row
    for (int idx = blockIdx.x * blockDim.x + threadIdx.x; idx < total;
         idx += gridDim.x * blockDim.x) {
        int i = idx / 10;
        int hg = idx - i * 10;
        const float4* s4 = reinterpret_cast<const float4*>(s + (size_t)i * NIN);
        float4 acc = make_float4(0.f, 0.f, 0.f, 0.f);
#pragma unroll
        for (int j = 0; j < 25; j++) {
            float4 v = __ldg(s4 + j);
            float4 w0 = *reinterpret_cast<const float4*>(&wxT[4 * j + 0][hg * 4]);
            float4 w1 = *reinterpret_cast<const float4*>(&wxT[4 * j + 1][hg * 4]);
            float4 w2 = *reinterpret_cast<const float4*>(&wxT[4 * j + 2][hg * 4]);
            float4 w3 = *reinterpret_cast<const float4*>(&wxT[4 * j + 3][hg * 4]);
            acc.x = fmaf(v.x, w0.x, fmaf(v.y, w1.x, fmaf(v.z, w2.x, fmaf(v.w, w3.x, acc.x))));
            acc.y = fmaf(v.x, w0.y, fmaf(v.y, w1.y, fmaf(v.z, w2.y, fmaf(v.w, w3.y, acc.y))));
            acc.z = fmaf(v.x, w0.z, fmaf(v.y, w1.z, fmaf(v.z, w2.z, fmaf(v.w, w3.z, acc.z))));
            acc.w = fmaf(v.x, w0.w, fmaf(v.y, w1.w, fmaf(v.z, w2.w, fmaf(v.w, w3.w, acc.w))));
        }
        *reinterpret_cast<float4*>(g_A + (size_t)i * NHID + hg * 4) = acc;
    }
}

// ---------------- Kernel 2: sequential scan (single block, latency-bound) --
// 64 threads (2 warps), 40 active. Thread h computes the FULL dot(Wh[h,:], t)
// with 20 packed f32x2 FMAs in 4 accumulator chains (no shuffle combine).
// t double-buffered in SMEM, one __syncthreads per step.
// A[] prefetched PF steps ahead into a register ring. Fast ex2/rcp tanh.
__global__ void rnn_scan_kernel(const float* __restrict__ t0,
                                const float* __restrict__ Wh,
                                float* __restrict__ outT) {
    __shared__ __align__(16) float ts[2][NHID];
    const int tid = threadIdx.x;                 // 64 threads
    const bool act = (tid < NHID);
    const int h = act ? tid : (NHID - 1);        // clamp keeps spares in-bounds

    if (tid < NHID) ts[0][tid] = t0[tid];

    // This thread's 40 Wh weights as 10 x (f32x2 pair): ulonglong2 loads.
    // Row offset h*160B is 16B-aligned.
    ulonglong2 wv[10];
    {
        const ulonglong2* wr = reinterpret_cast<const ulonglong2*>(Wh + h * NHID);
#pragma unroll
        for (int k = 0; k < 10; k++) wv[k] = wr[k];
    }

    const float* Ap = g_A + h;
    float* Tp = g_T + h;

    float apf[PF];
#pragma unroll
    for (int k = 0; k < PF; k++) apf[k] = __ldg(Ap + k * NHID);

    float tn = 0.f;
    __syncthreads();

    for (int i = 0; i < SEQ; i += PF) {
#pragma unroll
        for (int u = 0; u < PF; u++) {
            const int rb = u & 1, wb = rb ^ 1;
            const ulonglong2* tp = reinterpret_cast<const ulonglong2*>(ts[rb]);
            // 10 x LDS.128 (all lanes same address -> broadcast, conflict-free)
            ulonglong2 p0 = tp[0], p1 = tp[1], p2 = tp[2], p3 = tp[3], p4 = tp[4];
            ulonglong2 p5 = tp[5], p6 = tp[6], p7 = tp[7], p8 = tp[8], p9 = tp[9];

            // 20 packed FMAs, 4 independent chains of depth 5
            unsigned long long a0 = mul2(wv[0].x, p0.x);
            unsigned long long a1 = mul2(wv[0].y, p0.y);
            unsigned long long a2 = mul2(wv[1].x, p1.x);
            unsigned long long a3 = mul2(wv[1].y, p1.y);
            a0 = fma2(wv[2].x, p2.x, a0);
            a1 = fma2(wv[2].y, p2.y, a1);
            a2 = fma2(wv[3].x, p3.x, a2);
            a3 = fma2(wv[3].y, p3.y, a3);
            a0 = fma2(wv[4].x, p4.x, a0);
            a1 = fma2(wv[4].y, p4.y, a1);
            a2 = fma2(wv[5].x, p5.x, a2);
            a3 = fma2(wv[5].y, p5.y, a3);
            a0 = fma2(wv[6].x, p6.x, a0);
            a1 = fma2(wv[6].y, p6.y, a1);
            a2 = fma2(wv[7].x, p7.x, a2);
            a3 = fma2(wv[7].y, p7.y, a3);
            a0 = fma2(wv[8].x, p8.x, a0);
            a1 = fma2(wv[8].y, p8.y, a1);
            a2 = fma2(wv[9].x, p9.x, a2);
            a3 = fma2(wv[9].y, p9.y, a3);

            a0 = add2(a0, a1);
            a2 = add2(a2, a3);
            a0 = add2(a0, a2);
            float2 f = unpack2(a0);
            float z = (f.x + f.y) + apf[u];

            tn = fast_tanh(z);

            if (act) {
                ts[wb][h] = tn;
                Tp[(i + u) * NHID] = tn;     // fire-and-forget store of t_i
            }
            // prefetch A for step i+u+PF (clamped; off critical path)
            int nx = i + u + PF;
            if (nx > SEQ - 1) nx = SEQ - 1;
            apf[u] = __ldg(Ap + nx * NHID);

            __syncthreads();
        }
    }
    if (outT != nullptr && act) outT[h] = tn;    // t_{SEQ-1}
}

// ---------------- Kernel 3: y[i] = softmax(Wy @ t_i) ----------------
// One warp per row; lane computes outputs k = c*32 + lane, c = 0..3.
// Wy padded to stride 44 so every dot is 10 x LDS.128.
__global__ void rnn_softmax_kernel(const float* __restrict__ Wy,
                                   float* __restrict__ outY) {
    __shared__ __align__(16) float wy[NIN * 44];     // 17.6 KB, float4-aligned rows
    __shared__ __align__(16) float trow[4][NHID];    // one t row per warp
    for (int k = threadIdx.x; k < NIN * NHID; k += blockDim.x) {
        int r = k / NHID, c = k - r * NHID;
        wy[r * 44 + c] = Wy[k];
    }
    __syncthreads();

    const int warp = threadIdx.x >> 5;
    const int lane = threadIdx.x & 31;
    const float NEG_INF = -__int_as_float(0x7f800000);

    for (int row = blockIdx.x * 4 + warp; row < SEQ; row += gridDim.x * 4) {
        if (lane < 10)
            reinterpret_cast<float4*>(trow[warp])[lane] =
                reinterpret_cast<const float4*>(g_T + (size_t)row * NHID)[lane];
        __syncwarp();

        float z[4];
#pragma unroll
        for (int c = 0; c < 4; c++) {
            int k = c * 32 + lane;
            if (k < NIN) {
                const float4* w4 = reinterpret_cast<const float4*>(wy + k * 44);
                const float4* t4 = reinterpret_cast<const float4*>(trow[warp]);
                float acc = 0.f;
#pragma unroll
                for (int j = 0; j < 10; j++) {
                    float4 w = w4[j];
                    float4 t = t4[j];
                    acc = fmaf(w.x, t.x, fmaf(w.y, t.y, fmaf(w.z, t.z, fmaf(w.w, t.w, acc))));
                }
                z[c] = acc;
            } else {
                z[c] = NEG_INF;
            }
        }
        float m = fmaxf(fmaxf(z[0], z[1]), fmaxf(z[2], z[3]));
#pragma unroll
        for (int o = 16; o; o >>= 1)
            m = fmaxf(m, __shfl_xor_sync(0xFFFFFFFFu, m, o));

        float e[4];
        float ssum = 0.f;
#pragma unroll
        for (int c = 0; c < 4; c++) {
            e[c] = (z[c] > -1e30f) ? __expf(z[c] - m) : 0.f;
            ssum += e[c];
        }
#pragma unroll
        for (int o = 16; o; o >>= 1)
            ssum += __shfl_xor_sync(0xFFFFFFFFu, ssum, o);
        float inv = 1.0f / ssum;

#pragma unroll
        for (int c = 0; c < 4; c++) {
            int k = c * 32 + lane;
            if (k < NIN) outY[(size_t)row * NIN + k] = e[c] * inv;
        }
        __syncwarp();  // trow reused next iteration
    }
}

// ---------------- launch ----------------
extern "C" void kernel_launch(void* const* d_in, const int* in_sizes, int n_in,
                              void* d_out, int out_size) {
    const float* s  = (const float*)d_in[0];   // [262144,100]
    const float* t0 = (const float*)d_in[1];   // [40]
    const float* Wx = (const float*)d_in[2];   // [40,100]
    const float* Wh = (const float*)d_in[3];   // [40,40]
    const float* Wy = (const float*)d_in[4];   // [100,40]
    float* out = (float*)d_out;

    // Output tuple is (t_final, ys). Be defensive in case only ys is kept.
    float* tout;
    float* yout;
    if (out_size == SEQ * NIN) {
        tout = nullptr;
        yout = out;
    } else {
        tout = out;            // first 40 floats
        yout = out + NHID;     // then [262144,100]
    }

    rnn_pre_kernel<<<2048, 256>>>(s, Wx);
    rnn_scan_kernel<<<1, 64>>>(t0, Wh, tout);
    rnn_softmax_kernel<<<1184, 128>>>(Wy, yout);
}